// round 11
// baseline (speedup 1.0000x reference)
#include <cuda_runtime.h>
#include <math.h>

#define NN 1024
#define DD 64
#define DPP 32
#define NB_TILE 136
#define NB_BNOUT 64

// ---------------- scratch (device globals) ---------------------------------
__device__ float    g_dH[NN * NN];        // 4 MB pairwise H distances (mirrored)
__device__ float    g_dP[NN * NN];        // 4 MB pairwise P distances (mirrored)
__device__ unsigned g_mask [NN * 32];     // row-major top-K bitset (fully overwritten)
__device__ unsigned g_maskT[NN * 32];     // transposed bitset (atomicOr; zeroed in k_dist)
__device__ float    g_bmxH[NB_TILE];      // per-H-block max
__device__ float    g_bmxP[NB_TILE];      // per-P-block max
__device__ float    g_bnp[NB_BNOUT][2][DD];  // per-block BN partials (s1, s2)
__device__ unsigned g_arrive;             // bnout arrival counter (zeroed in k_dist)

// ---------------- 1. distances: 272 blocks (136 H + 136 P), 4x4 micro ------
__global__ __launch_bounds__(256)
void k_dist(const float* __restrict__ XH, const float* __restrict__ XP) {
    __shared__ float pool[4224];          // 16.9 KB, phase-aliased
    __shared__ unsigned smx[8];
    int t = threadIdx.x;

    // init: blocks 0..127 zero maskT (1 word/thread); block 0 resets arrive
    if ((int)blockIdx.x < 128) {
        g_maskT[blockIdx.x * 256 + t] = 0u;
        if (blockIdx.x == 0 && t == 0) g_arrive = 0u;
    }

    int isH = ((int)blockIdx.x < NB_TILE);
    int tid = isH ? blockIdx.x : blockIdx.x - NB_TILE;

    // decode upper-triangle tile index (by <= bx over 16x16 tiles)
    int by = 0, rem = tid;
    while (rem >= 16 - by) { rem -= 16 - by; ++by; }
    int bx = by + rem;
    int i0 = by * 64, j0 = bx * 64;
    int tx = t & 15, ty = t >> 4;

    float acc[4][4];
    #pragma unroll
    for (int a = 0; a < 4; ++a)
        #pragma unroll
        for (int b = 0; b < 4; ++b) acc[a][b] = 0.f;

    float* sA = pool;                     // [64][33]
    float* sB = pool + 2112;              // [64][33]

    if (isH) {
        const float sig = (float)(0.1 + 2.220446049250313e-16);  // sigma + f64 eps
        #pragma unroll
        for (int h = 0; h < 2; ++h) {     // two 32-dim halves, d ascending
            __syncthreads();
            for (int idx = t; idx < 2048; idx += 256) {
                int r = idx >> 5, d = idx & 31;
                sA[r * 33 + d] = XH[(i0 + r) * 64 + h * 32 + d] / sig;
                sB[r * 33 + d] = XH[(j0 + r) * 64 + h * 32 + d] / sig;
            }
            __syncthreads();
            #pragma unroll 8
            for (int d = 0; d < 32; ++d) {
                float rI[4], rJ[4];
                #pragma unroll
                for (int a = 0; a < 4; ++a) rI[a] = sA[(ty + 16 * a) * 33 + d];
                #pragma unroll
                for (int b = 0; b < 4; ++b) rJ[b] = sB[(tx + 16 * b) * 33 + d];
                #pragma unroll
                for (int a = 0; a < 4; ++a)
                    #pragma unroll
                    for (int b = 0; b < 4; ++b) {
                        float df = rI[a] - rJ[b];
                        acc[a][b] += df * df;
                    }
            }
        }
    } else {
        for (int idx = t; idx < 2048; idx += 256) {
            int r = idx >> 5, p = idx & 31;
            sA[r * 33 + p] = XP[(i0 + r) * 32 + p];
            sB[r * 33 + p] = XP[(j0 + r) * 32 + p];
        }
        __syncthreads();
        #pragma unroll 8
        for (int p = 0; p < 32; ++p) {
            float rI[4], rJ[4];
            #pragma unroll
            for (int a = 0; a < 4; ++a) rI[a] = sA[(ty + 16 * a) * 33 + p];
            #pragma unroll
            for (int b = 0; b < 4; ++b) rJ[b] = sB[(tx + 16 * b) * 33 + p];
            #pragma unroll
            for (int a = 0; a < 4; ++a)
                #pragma unroll
                for (int b = 0; b < 4; ++b) {
                    float df = rI[a] - rJ[b];
                    acc[a][b] += df * df;
                }
        }
    }

    float* dst = isH ? g_dH : g_dP;

    // sqrt, straight write, per-block max
    float res[4][4];
    unsigned lmx = 0u;
    #pragma unroll
    for (int a = 0; a < 4; ++a)
        #pragma unroll
        for (int b = 0; b < 4; ++b) {
            float dv = sqrtf(acc[a][b]);
            res[a][b] = dv;
            lmx = max(lmx, __float_as_uint(dv));
            dst[(i0 + ty + 16 * a) * NN + (j0 + tx + 16 * b)] = dv;
        }
    lmx = __reduce_max_sync(0xffffffffu, lmx);
    if ((t & 31) == 0) smx[t >> 5] = lmx;
    __syncthreads();
    if (t == 0) {
        unsigned h = 0u;
        #pragma unroll
        for (int wv = 0; wv < 8; ++wv) h = max(h, smx[wv]);
        if (isH) g_bmxH[tid] = __uint_as_float(h);
        else     g_bmxP[tid] = __uint_as_float(h);
    }

    // mirror via two half-tile shared transposes (coalesced both ways)
    if (bx != by) {
        float (*st)[33] = (float(*)[33])pool;     // [64][33], i-half of 32
        #pragma unroll
        for (int h = 0; h < 2; ++h) {
            __syncthreads();
            #pragma unroll
            for (int a = 2 * h; a < 2 * h + 2; ++a)
                #pragma unroll
                for (int b = 0; b < 4; ++b)
                    st[tx + 16 * b][ty + 16 * a - 32 * h] = res[a][b];
            __syncthreads();
            for (int idx = t; idx < 2048; idx += 256) {
                int r = idx >> 5, c = idx & 31;
                dst[(j0 + r) * NN + (i0 + 32 * h + c)] = st[r][c];
            }
        }
    }
}

// ---------------- 2. fused WW + exact top-K (one warp per row) -------------
__global__ void k_topk(const int* __restrict__ Kp) {
    __shared__ unsigned sredH[8], sredP[8];
    int t = threadIdx.x, lane = t & 31, w = t >> 5;
    int i = blockIdx.x * 8 + w;

    // reduce per-block maxes -> global max (prologue)
    {
        unsigned h = 0u, p = 0u;
        if (t < NB_TILE) {
            h = __float_as_uint(g_bmxH[t]);
            p = __float_as_uint(g_bmxP[t]);
        }
        h = __reduce_max_sync(0xffffffffu, h);
        p = __reduce_max_sync(0xffffffffu, p);
        if (lane == 0) { sredH[w] = h; sredP[w] = p; }
    }
    __syncthreads();
    unsigned hh = 0u, pp = 0u;
    #pragma unroll
    for (int s = 0; s < 8; ++s) { hh = max(hh, sredH[s]); pp = max(pp, sredP[s]); }
    float invH = 0.5f / __uint_as_float(hh);   // min is exactly 0 (diagonal)
    float invP = 1.0f / __uint_as_float(pp);

    // load row, compute WW keys (WW > 0 -> float bits are uint-ordered)
    unsigned key[32];
    #pragma unroll
    for (int s = 0; s < 32; ++s) {
        float dh = g_dH[i * NN + s * 32 + lane];
        float dp = g_dP[i * NN + s * 32 + lane];
        float ww = expf(-dh * invH) + 0.2f * expf(-dp * invP);
        key[s] = __float_as_uint(ww);
    }

    int K = Kp ? Kp[0] : 16;
    if (K < 1) K = 1; if (K > NN) K = NN;

    unsigned mrow = 0u;                   // lane L accumulates mask word L
    for (int it = 0; it < K; ++it) {
        unsigned lm = 0u;
        #pragma unroll
        for (int s = 0; s < 32; ++s) lm = max(lm, key[s]);
        unsigned wm = __reduce_max_sync(0xffffffffu, lm);
        // lowest j holding wm (exact jax tie semantics)
        int jc = 0x7fffffff;
        #pragma unroll
        for (int s = 0; s < 32; ++s)
            if (key[s] == wm && s * 32 + lane < jc) jc = s * 32 + lane;
        int jmin = __reduce_min_sync(0xffffffffu, (unsigned)jc);
        // remove from owner lane WITHOUT dynamic register indexing (no spill)
        int ssel = jmin >> 5;
        if (lane == (jmin & 31)) {
            #pragma unroll
            for (int s = 0; s < 32; ++s)
                if (s == ssel) key[s] = 0u;
        }
        if (lane == ssel) mrow |= 1u << (jmin & 31);
        if (lane == 0)
            atomicOr(&g_maskT[jmin * 32 + (i >> 5)], 1u << (i & 31));
    }
    g_mask[i * 32 + lane] = mrow;
}

// ---------------- 3. merged xy + deg + BN + output (64 blocks) -------------
__global__ __launch_bounds__(256)
void k_bnout(const float* __restrict__ XX, const float* __restrict__ W,
             const float* __restrict__ PW,
             const float* __restrict__ psi_b, const float* __restrict__ gamma,
             const float* __restrict__ beta, const float* __restrict__ bias,
             const float* __restrict__ XP, float* __restrict__ out) {
    __shared__ float sW[4096];            // [k*64+d]; later aliased: sy/sp1/sp2
    __shared__ float sPW[4160];           // [d*65+k]; later aliased: ss/smu etc
    __shared__ float sXB[1024];           // XX rows -> x rows (aliased)
    __shared__ int   sc[16], sdg[16];
    int t = threadIdx.x, lane = t & 31, w = t >> 5;
    int j0 = blockIdx.x * 16;

    // aliases into sW after GEMMs are done with it
    float* sy  = sW;                      // [16][64]
    float* sp1 = sW + 1024;               // [16][64]
    float* sp2 = sW + 2048;               // [16][64]
    // aliases into sPW after GEMM2
    float (*ss1)[64] = (float(*)[64])sPW;            // [4][64]
    float (*ss2)[64] = (float(*)[64])(sPW + 256);    // [4][64]
    float* smu   = sPW + 512;
    float* sistd = sPW + 576;
    float* sg    = sPW + 640;
    float* sb    = sPW + 704;
    float* sbi   = sPW + 768;
    float* spb   = sPW + 832;
    float* sx    = sXB;                   // x rows after alias

    // phase 0a: weights + own XX rows
    for (int idx = t; idx < 4096; idx += 256) sW[idx] = W[idx];
    for (int idx = t; idx < 4096; idx += 256) {
        int d = idx >> 6, k = idx & 63;
        sPW[d * 65 + k] = PW[idx];
    }
    for (int idx = t; idx < 1024; idx += 256) sXB[idx] = XX[j0 * 64 + idx];

    // phase A: degrees + diag for own 16 j's (warp w: 2 j's, loads batched)
    {
        int ja = j0 + w * 2, jb = ja + 1;
        unsigned ma = g_mask[ja * 32 + lane] | g_maskT[ja * 32 + lane];
        unsigned mb = g_mask[jb * 32 + lane] | g_maskT[jb * 32 + lane];
        int ca = __reduce_add_sync(0xffffffffu, __popc(ma));
        int cb = __reduce_add_sync(0xffffffffu, __popc(mb));
        int da = __shfl_sync(0xffffffffu, (int)((ma >> (ja & 31)) & 1u), ja >> 5);
        int db = __shfl_sync(0xffffffffu, (int)((mb >> (jb & 31)) & 1u), jb >> 5);
        if (lane == 0) {
            sc[ja - j0] = ca; sc[jb - j0] = cb;
            sdg[ja - j0] = da; sdg[jb - j0] = db;
        }
    }
    __syncthreads();

    // phase 0b: x = XX@W (16 rows), then y = x@PW^T; k ascending (bit-exact)
    int d = t & 63, rg = t >> 6;          // 4 row-groups x 4 rows
    float acc[4] = {0.f, 0.f, 0.f, 0.f};
    #pragma unroll
    for (int k = 0; k < 64; ++k) {
        float wv = sW[k * 64 + d];
        #pragma unroll
        for (int rr = 0; rr < 4; ++rr) acc[rr] += sXB[(rg * 4 + rr) * 64 + k] * wv;
    }
    __syncthreads();                      // done reading sXB (as XX) and sW
    #pragma unroll
    for (int rr = 0; rr < 4; ++rr) sx[(rg * 4 + rr) * 64 + d] = acc[rr];
    __syncthreads();

    float a2[4] = {0.f, 0.f, 0.f, 0.f};
    #pragma unroll
    for (int k = 0; k < 64; ++k) {
        float pw = sPW[d * 65 + k];
        #pragma unroll
        for (int rr = 0; rr < 4; ++rr) a2[rr] += sx[(rg * 4 + rr) * 64 + k] * pw;
    }
    __syncthreads();                      // done reading sPW; sW free -> sy
    #pragma unroll
    for (int rr = 0; rr < 4; ++rr) sy[(rg * 4 + rr) * 64 + d] = a2[rr];
    __syncthreads();

    // phase B: BN partials over own 16 rows
    int jl = t >> 4, d0 = (t & 15) * 4;
    {
        float c = (float)sc[jl];
        #pragma unroll
        for (int u = 0; u < 4; ++u) {
            float yv = sy[jl * 64 + d0 + u];
            float bb = psi_b[d0 + u];
            sp1[jl * 64 + d0 + u] = yv * ((float)NN + c);
            float h1 = yv + bb, h2 = 2.f * yv + bb;
            sp2[jl * 64 + d0 + u] = ((float)NN - c) * h1 * h1 + c * h2 * h2;
        }
    }
    __syncthreads();
    {
        float a1 = sp1[rg * 64 + d] + sp1[(rg + 4) * 64 + d]
                 + sp1[(rg + 8) * 64 + d] + sp1[(rg + 12) * 64 + d];
        float b1 = sp2[rg * 64 + d] + sp2[(rg + 4) * 64 + d]
                 + sp2[(rg + 8) * 64 + d] + sp2[(rg + 12) * 64 + d];
        ss1[rg][d] = a1; ss2[rg][d] = b1;
    }
    __syncthreads();
    if (t < 64) {
        g_bnp[blockIdx.x][0][t] = ss1[0][t] + ss1[1][t] + ss1[2][t] + ss1[3][t];
        g_bnp[blockIdx.x][1][t] = ss2[0][t] + ss2[1][t] + ss2[2][t] + ss2[3][t];
    }
    __syncthreads();
    if (t == 0) {
        __threadfence();                  // release partials
        atomicAdd(&g_arrive, 1u);
        while (*(volatile unsigned*)&g_arrive < NB_BNOUT) { }   // 64 co-resident
        __threadfence();                  // acquire partials
    }
    __syncthreads();

    // phase C: redundant parallel finalize (32 KB L2-hot per block)
    if (t < 64) {
        float s1 = 0.f, s2 = 0.f;
        #pragma unroll 4
        for (int bl = 0; bl < NB_BNOUT; ++bl) {
            s1 += g_bnp[bl][0][t];
            s2 += g_bnp[bl][1][t];
        }
        const float invN2 = 1.0f / ((float)NN * (float)NN);
        float mu  = psi_b[t] + s1 * invN2;
        float var = s2 * invN2 - mu * mu;
        smu[t]   = mu;
        sistd[t] = rsqrtf(var + 1e-5f);
        sg[t] = gamma[t]; sb[t] = beta[t]; sbi[t] = bias[t]; spb[t] = psi_b[t];
    }
    __syncthreads();

    // phase D: output slice (rows == own rows)
    int q = blockIdx.x * 256 + t;         // global float4 slot
    float dg = (float)sdg[jl], c = (float)sc[jl];
    float4 o4;
    float* ov = (float*)&o4;
    #pragma unroll
    for (int u = 0; u < 4; ++u) {
        int dd = d0 + u;
        float yv = sy[jl * 64 + dd];
        float xv = sx[jl * 64 + dd];
        float z = (2.f * yv + spb[dd] - smu[dd]) * sistd[dd] * sg[dd] + sb[dd];
        float s = 1.0f / (1.0f + expf(-z));
        ov[u] = xv * (dg + (c - dg) * s) + sbi[dd];
    }
    ((float4*)out)[q] = o4;                               // out[:, :DH] segment
    ((float4*)(out + NN * DD + NN * DPP))[q] = o4;        // full out segment
    if (q < NN * DPP / 4)
        ((float4*)(out + NN * DD))[q] = ((const float4*)XP)[q];  // XP passthrough
}

// ---------------- launch ----------------------------------------------------
extern "C" void kernel_launch(void* const* d_in, const int* in_sizes, int n_in,
                              void* d_out, int out_size) {
    // expected order: XH, XP, XX, K, weight, bias, psi_w, psi_b, gamma, beta
    int iXH = 0, iXP = 1, iXX = 2, iK = 3, iW = 4, iB = 5, iPW = 6, iPB = 7, iG = 8, iBe = 9;
    if (n_in == 9) {  // K dropped as a scalar
        iK = -1; iW = 3; iB = 4; iPW = 5; iPB = 6; iG = 7; iBe = 8;
    }
    const float* XH  = (const float*)d_in[iXH];
    const float* XP  = (const float*)d_in[iXP];
    const float* XX  = (const float*)d_in[iXX];
    const int*   Kp  = (iK >= 0) ? (const int*)d_in[iK] : nullptr;
    const float* W   = (const float*)d_in[iW];
    const float* B   = (const float*)d_in[iB];
    const float* PW  = (const float*)d_in[iPW];
    const float* PB  = (const float*)d_in[iPB];
    const float* G   = (const float*)d_in[iG];
    const float* Be  = (const float*)d_in[iBe];
    float* out = (float*)d_out;

    k_dist <<<2 * NB_TILE, 256>>>(XH, XP);
    k_topk <<<128, 256>>>(Kp);
    k_bnout<<<NB_BNOUT, 256>>>(XX, W, PW, PB, G, Be, B, XP, out);
    (void)in_sizes; (void)out_size;
}

// round 12
// speedup vs baseline: 1.1746x; 1.1746x over previous
#include <cuda_runtime.h>
#include <math.h>

#define NN 1024
#define DD 64
#define DPP 32
#define NB_DIST 136
#define NB_BNOUT 64

// ---------------- scratch (device globals) ---------------------------------
__device__ float2   g_d2[NN * NN];        // 8 MB: (dH, dP) pairwise, full mirrored
__device__ unsigned g_mask [NN * 32];     // row-major top-K bitset (fully overwritten)
__device__ unsigned g_maskT[NN * 32];     // transposed bitset (atomicOr; zeroed in k_main)
__device__ float    g_x[NN * DD];         // XX @ weight
__device__ float    g_y[NN * DD];         // x @ psi_w^T
__device__ float2   g_bmx[NB_DIST];       // per-dist-block (maxH, maxP)
__device__ float    g_bnp[NB_BNOUT][2][DD];  // per-block BN partials (s1, s2)
__device__ unsigned g_arrive;             // bnout arrival counter (zeroed in k_main)

// ---------------- 1. merged: dist (blocks 0..135) + xy/init (136..199) -----
__global__ __launch_bounds__(256)
void k_main(const float* __restrict__ XH, const float* __restrict__ XP,
            const float* __restrict__ XX, const float* __restrict__ W,
            const float* __restrict__ PW) {
    __shared__ float pool[10304];         // 41.2 KB, phase-aliased
    __shared__ float sNA[64], sNB[64], sPA[64], sPB[64];
    __shared__ unsigned smx[8], smp[8];
    int t = threadIdx.x;

    if ((int)blockIdx.x >= NB_DIST) {
        // ---------------- xy body + init ----------------
        int xb = blockIdx.x - NB_DIST;    // 0..63
        int gt = xb * 256 + t;            // 16384 threads
        g_maskT[gt * 2]     = 0u;
        g_maskT[gt * 2 + 1] = 0u;
        if (gt == 0) g_arrive = 0u;

        float* sW  = pool;                // [k*64+d], 4096
        float* sPW = pool + 4096;         // [d*65+k], 4160 (padded)
        float* sXX = pool + 8256;         // 1024
        float* sx  = pool + 9280;         // 1024
        int row0 = xb * 16;

        for (int idx = t; idx < 4096; idx += 256) sW[idx] = W[idx];
        for (int idx = t; idx < 4096; idx += 256) {
            int d = idx >> 6, k = idx & 63;
            sPW[d * 65 + k] = PW[idx];
        }
        for (int idx = t; idx < 1024; idx += 256) sXX[idx] = XX[row0 * 64 + idx];
        __syncthreads();

        int d = t & 63, rg = t >> 6;
        float acc[4] = {0.f, 0.f, 0.f, 0.f};
        #pragma unroll
        for (int k = 0; k < 64; ++k) {
            float wv = sW[k * 64 + d];
            #pragma unroll
            for (int rr = 0; rr < 4; ++rr) acc[rr] += sXX[(rg * 4 + rr) * 64 + k] * wv;
        }
        #pragma unroll
        for (int rr = 0; rr < 4; ++rr) {
            sx[(rg * 4 + rr) * 64 + d] = acc[rr];
            g_x[(row0 + rg * 4 + rr) * 64 + d] = acc[rr];
        }
        __syncthreads();

        float a2[4] = {0.f, 0.f, 0.f, 0.f};
        #pragma unroll
        for (int k = 0; k < 64; ++k) {
            float pw = sPW[d * 65 + k];
            #pragma unroll
            for (int rr = 0; rr < 4; ++rr) a2[rr] += sx[(rg * 4 + rr) * 64 + k] * pw;
        }
        #pragma unroll
        for (int rr = 0; rr < 4; ++rr) g_y[(row0 + rg * 4 + rr) * 64 + d] = a2[rr];
        return;
    }

    // ---------------- dist body: norm + dot trick, 4x4 micro-tile ----------
    int by = 0, rem = blockIdx.x;
    while (rem >= 16 - by) { rem -= 16 - by; ++by; }
    int bx = by + rem;
    int i0 = by * 64, j0 = bx * 64;
    int tx = t & 15, ty = t >> 4;
    const float sig = (float)(0.1 + 2.220446049250313e-16);  // sigma + float64 eps

    // phase 1: H features (64 dims)
    float (*sA)[65] = (float(*)[65])pool;
    float (*sB)[65] = (float(*)[65])(pool + 64 * 65);
    for (int idx = t; idx < 4096; idx += 256) {
        int r = idx >> 6, d = idx & 63;
        sA[r][d] = XH[(i0 + r) * 64 + d] / sig;
        sB[r][d] = XH[(j0 + r) * 64 + d] / sig;
    }
    __syncthreads();

    // H row norms (threads 0..127, 4 partial chains)
    if (t < 128) {
        const float* rp = (t < 64) ? &sA[t][0] : &sB[t - 64][0];
        float n0 = 0.f, n1 = 0.f, n2 = 0.f, n3 = 0.f;
        #pragma unroll
        for (int d = 0; d < 64; d += 4) {
            n0 += rp[d] * rp[d];
            n1 += rp[d + 1] * rp[d + 1];
            n2 += rp[d + 2] * rp[d + 2];
            n3 += rp[d + 3] * rp[d + 3];
        }
        float nv = (n0 + n1) + (n2 + n3);
        if (t < 64) sNA[t] = nv; else sNB[t - 64] = nv;
    }

    float accH[4][4];
    #pragma unroll
    for (int a = 0; a < 4; ++a)
        #pragma unroll
        for (int b = 0; b < 4; ++b) accH[a][b] = 0.f;
    #pragma unroll 8
    for (int d = 0; d < 64; ++d) {
        float rI[4], rJ[4];
        #pragma unroll
        for (int a = 0; a < 4; ++a) rI[a] = sA[ty + 16 * a][d];
        #pragma unroll
        for (int b = 0; b < 4; ++b) rJ[b] = sB[tx + 16 * b][d];
        #pragma unroll
        for (int a = 0; a < 4; ++a)
            #pragma unroll
            for (int b = 0; b < 4; ++b)
                accH[a][b] += rI[a] * rJ[b];
    }
    __syncthreads();

    // phase 2: P features (32 dims), reuse pool
    float (*pA)[33] = (float(*)[33])pool;
    float (*pB)[33] = (float(*)[33])(pool + 64 * 33);
    for (int idx = t; idx < 2048; idx += 256) {
        int r = idx >> 5, p = idx & 31;
        pA[r][p] = XP[(i0 + r) * 32 + p];
        pB[r][p] = XP[(j0 + r) * 32 + p];
    }
    __syncthreads();

    // P row norms
    if (t < 128) {
        const float* rp = (t < 64) ? &pA[t][0] : &pB[t - 64][0];
        float n0 = 0.f, n1 = 0.f, n2 = 0.f, n3 = 0.f;
        #pragma unroll
        for (int p = 0; p < 32; p += 4) {
            n0 += rp[p] * rp[p];
            n1 += rp[p + 1] * rp[p + 1];
            n2 += rp[p + 2] * rp[p + 2];
            n3 += rp[p + 3] * rp[p + 3];
        }
        float nv = (n0 + n1) + (n2 + n3);
        if (t < 64) sPA[t] = nv; else sPB[t - 64] = nv;
    }

    float accP[4][4];
    #pragma unroll
    for (int a = 0; a < 4; ++a)
        #pragma unroll
        for (int b = 0; b < 4; ++b) accP[a][b] = 0.f;
    #pragma unroll 8
    for (int p = 0; p < 32; ++p) {
        float rI[4], rJ[4];
        #pragma unroll
        for (int a = 0; a < 4; ++a) rI[a] = pA[ty + 16 * a][p];
        #pragma unroll
        for (int b = 0; b < 4; ++b) rJ[b] = pB[tx + 16 * b][p];
        #pragma unroll
        for (int a = 0; a < 4; ++a)
            #pragma unroll
            for (int b = 0; b < 4; ++b)
                accP[a][b] += rI[a] * rJ[b];
    }
    __syncthreads();                      // norms visible

    // phase 3: d = sqrt(max(nI + nJ - 2*dot, 0)), write, per-block max
    float nHa[4], nHb[4], nPa[4], nPb[4];
    #pragma unroll
    for (int a = 0; a < 4; ++a) { nHa[a] = sNA[ty + 16 * a]; nPa[a] = sPA[ty + 16 * a]; }
    #pragma unroll
    for (int b = 0; b < 4; ++b) { nHb[b] = sNB[tx + 16 * b]; nPb[b] = sPB[tx + 16 * b]; }

    float2 res[4][4];
    unsigned lmH = 0u, lmP = 0u;
    #pragma unroll
    for (int a = 0; a < 4; ++a)
        #pragma unroll
        for (int b = 0; b < 4; ++b) {
            float dh = sqrtf(fmaxf(nHa[a] + nHb[b] - 2.f * accH[a][b], 0.f));
            float dp = sqrtf(fmaxf(nPa[a] + nPb[b] - 2.f * accP[a][b], 0.f));
            res[a][b] = make_float2(dh, dp);
            lmH = max(lmH, __float_as_uint(dh));
            lmP = max(lmP, __float_as_uint(dp));
            g_d2[(i0 + ty + 16 * a) * NN + (j0 + tx + 16 * b)] = res[a][b];
        }
    lmH = __reduce_max_sync(0xffffffffu, lmH);
    lmP = __reduce_max_sync(0xffffffffu, lmP);
    if ((t & 31) == 0) { smx[t >> 5] = lmH; smp[t >> 5] = lmP; }
    __syncthreads();
    if (t == 0) {
        unsigned h = 0u, p = 0u;
        #pragma unroll
        for (int wv = 0; wv < 8; ++wv) { h = max(h, smx[wv]); p = max(p, smp[wv]); }
        g_bmx[blockIdx.x] = make_float2(__uint_as_float(h), __uint_as_float(p));
    }

    // phase 4: mirror tile via shared transpose (coalesced both ways)
    if (bx != by) {
        __syncthreads();                              // done reading P smem
        float2 (*st)[66] = (float2(*)[66])pool;
        #pragma unroll
        for (int a = 0; a < 4; ++a)
            #pragma unroll
            for (int b = 0; b < 4; ++b)
                st[tx + 16 * b][ty + 16 * a] = res[a][b];
        __syncthreads();
        for (int idx = t; idx < 4096; idx += 256) {
            int r = idx >> 6, c = idx & 63;
            g_d2[(j0 + r) * NN + (i0 + c)] = st[r][c];
        }
    }
}

// ---------------- 2. fused WW + exact top-K (one warp per row) -------------
__global__ void k_topk(const int* __restrict__ Kp) {
    __shared__ unsigned sredH[8], sredP[8];
    int t = threadIdx.x, lane = t & 31, w = t >> 5;
    int i = blockIdx.x * 8 + w;

    // reduce per-block maxes -> global max (prologue)
    {
        unsigned h = 0u, p = 0u;
        if (t < NB_DIST) {
            float2 v = g_bmx[t];
            h = __float_as_uint(v.x); p = __float_as_uint(v.y);
        }
        h = __reduce_max_sync(0xffffffffu, h);
        p = __reduce_max_sync(0xffffffffu, p);
        if (lane == 0) { sredH[w] = h; sredP[w] = p; }
    }
    __syncthreads();
    unsigned hh = 0u, pp = 0u;
    #pragma unroll
    for (int s = 0; s < 8; ++s) { hh = max(hh, sredH[s]); pp = max(pp, sredP[s]); }
    float invH = 0.5f / __uint_as_float(hh);   // min is exactly 0 (diagonal)
    float invP = 1.0f / __uint_as_float(pp);

    // load row, compute WW keys (WW > 0 -> float bits are uint-ordered)
    unsigned key[32];
    #pragma unroll
    for (int s = 0; s < 32; ++s) {
        float2 dv = g_d2[i * NN + s * 32 + lane];
        float ww = expf(-dv.x * invH) + 0.2f * expf(-dv.y * invP);
        key[s] = __float_as_uint(ww);
    }

    int K = Kp ? Kp[0] : 16;
    if (K < 1) K = 1; if (K > NN) K = NN;

    unsigned mrow = 0u;                   // lane L accumulates mask word L
    for (int it = 0; it < K; ++it) {
        unsigned lm = 0u;
        #pragma unroll
        for (int s = 0; s < 32; ++s) lm = max(lm, key[s]);
        unsigned wm = __reduce_max_sync(0xffffffffu, lm);
        // lowest j holding wm (exact jax tie semantics)
        int jc = 0x7fffffff;
        #pragma unroll
        for (int s = 0; s < 32; ++s)
            if (key[s] == wm && s * 32 + lane < jc) jc = s * 32 + lane;
        int jmin = __reduce_min_sync(0xffffffffu, (unsigned)jc);
        // remove from owner lane WITHOUT dynamic register indexing (no spill)
        int ssel = jmin >> 5;
        if (lane == (jmin & 31)) {
            #pragma unroll
            for (int s = 0; s < 32; ++s)
                if (s == ssel) key[s] = 0u;
        }
        if (lane == ssel) mrow |= 1u << (jmin & 31);
        if (lane == 0)
            atomicOr(&g_maskT[jmin * 32 + (i >> 5)], 1u << (i & 31));
    }
    g_mask[i * 32 + lane] = mrow;
}

// ---------------- 3. merged deg + BN + output (64 co-resident blocks) ------
__global__ void k_bnout(const float* __restrict__ psi_b, const float* __restrict__ gamma,
                        const float* __restrict__ beta, const float* __restrict__ bias,
                        const float* __restrict__ XP, float* __restrict__ out) {
    __shared__ int   sc[16], sdg[16];
    __shared__ float sp1[16][64], sp2[16][64];
    __shared__ float ss1[4][64], ss2[4][64];
    __shared__ float smu[64], sistd[64], sg[64], sb[64], sbi[64], spb[64];
    int t = threadIdx.x, lane = t & 31, w = t >> 5;
    int j0 = blockIdx.x * 16;

    // phase A: degrees + diag for own 16 j's (warp w: 2 j's, loads batched)
    {
        int ja = j0 + w * 2, jb = ja + 1;
        unsigned ma = g_mask[ja * 32 + lane] | g_maskT[ja * 32 + lane];
        unsigned mb = g_mask[jb * 32 + lane] | g_maskT[jb * 32 + lane];
        int ca = __reduce_add_sync(0xffffffffu, __popc(ma));
        int cb = __reduce_add_sync(0xffffffffu, __popc(mb));
        int da = __shfl_sync(0xffffffffu, (int)((ma >> (ja & 31)) & 1u), ja >> 5);
        int db = __shfl_sync(0xffffffffu, (int)((mb >> (jb & 31)) & 1u), jb >> 5);
        if (lane == 0) {
            sc[ja - j0] = ca; sc[jb - j0] = cb;
            sdg[ja - j0] = da; sdg[jb - j0] = db;
        }
    }
    __syncthreads();

    // phase B: BN partials over own 16 rows (float4 per thread)
    int q = blockIdx.x * 256 + t;         // global float4 slot; j = q>>4 in [j0, j0+16)
    int jl = t >> 4, d0 = (t & 15) * 4;
    float4 y4 = ((const float4*)g_y)[q];
    {
        float c = (float)sc[jl];
        float yv[4] = {y4.x, y4.y, y4.z, y4.w};
        #pragma unroll
        for (int u = 0; u < 4; ++u) {
            float bb = psi_b[d0 + u];
            sp1[jl][d0 + u] = yv[u] * ((float)NN + c);
            float h1 = yv[u] + bb, h2 = 2.f * yv[u] + bb;
            sp2[jl][d0 + u] = ((float)NN - c) * h1 * h1 + c * h2 * h2;
        }
    }
    __syncthreads();
    {
        int d = t & 63, rg = t >> 6;
        float a1 = sp1[rg][d] + sp1[rg + 4][d] + sp1[rg + 8][d] + sp1[rg + 12][d];
        float a2 = sp2[rg][d] + sp2[rg + 4][d] + sp2[rg + 8][d] + sp2[rg + 12][d];
        ss1[rg][d] = a1; ss2[rg][d] = a2;
    }
    __syncthreads();
    if (t < 64) {
        g_bnp[blockIdx.x][0][t] = ss1[0][t] + ss1[1][t] + ss1[2][t] + ss1[3][t];
        g_bnp[blockIdx.x][1][t] = ss2[0][t] + ss2[1][t] + ss2[2][t] + ss2[3][t];
    }
    __syncthreads();
    if (t == 0) {
        __threadfence();                  // release partials
        atomicAdd(&g_arrive, 1u);
        while (*(volatile unsigned*)&g_arrive < NB_BNOUT) { }   // all 64 co-resident
        __threadfence();                  // acquire partials
    }
    __syncthreads();

    // phase C: redundant parallel finalize (32 KB L2-hot per block)
    if (t < 64) {
        float s1 = 0.f, s2 = 0.f;
        #pragma unroll 4
        for (int bl = 0; bl < NB_BNOUT; ++bl) {
            s1 += g_bnp[bl][0][t];
            s2 += g_bnp[bl][1][t];
        }
        const float invN2 = 1.0f / ((float)NN * (float)NN);
        float mu  = psi_b[t] + s1 * invN2;
        float var = s2 * invN2 - mu * mu;
        smu[t]   = mu;
        sistd[t] = rsqrtf(var + 1e-5f);
        sg[t] = gamma[t]; sb[t] = beta[t]; sbi[t] = bias[t]; spb[t] = psi_b[t];
    }
    __syncthreads();

    // phase D: output slice (rows == own degree rows)
    float4 x4 = ((const float4*)g_x)[q];
    float dg = (float)sdg[jl], c = (float)sc[jl];
    float yv[4] = {y4.x, y4.y, y4.z, y4.w};
    float xv[4] = {x4.x, x4.y, x4.z, x4.w};
    float4 o4;
    float* ov = (float*)&o4;
    #pragma unroll
    for (int u = 0; u < 4; ++u) {
        int d = d0 + u;
        float z = (2.f * yv[u] + spb[d] - smu[d]) * sistd[d] * sg[d] + sb[d];
        float s = 1.0f / (1.0f + expf(-z));
        ov[u] = xv[u] * (dg + (c - dg) * s) + sbi[d];
    }
    ((float4*)out)[q] = o4;                               // out[:, :DH] segment
    ((float4*)(out + NN * DD + NN * DPP))[q] = o4;        // full out segment
    if (q < NN * DPP / 4)
        ((float4*)(out + NN * DD))[q] = ((const float4*)XP)[q];  // XP passthrough
}

// ---------------- launch ----------------------------------------------------
extern "C" void kernel_launch(void* const* d_in, const int* in_sizes, int n_in,
                              void* d_out, int out_size) {
    // expected order: XH, XP, XX, K, weight, bias, psi_w, psi_b, gamma, beta
    int iXH = 0, iXP = 1, iXX = 2, iK = 3, iW = 4, iB = 5, iPW = 6, iPB = 7, iG = 8, iBe = 9;
    if (n_in == 9) {  // K dropped as a scalar
        iK = -1; iW = 3; iB = 4; iPW = 5; iPB = 6; iG = 7; iBe = 8;
    }
    const float* XH  = (const float*)d_in[iXH];
    const float* XP  = (const float*)d_in[iXP];
    const float* XX  = (const float*)d_in[iXX];
    const int*   Kp  = (iK >= 0) ? (const int*)d_in[iK] : nullptr;
    const float* W   = (const float*)d_in[iW];
    const float* B   = (const float*)d_in[iB];
    const float* PW  = (const float*)d_in[iPW];
    const float* PB  = (const float*)d_in[iPB];
    const float* G   = (const float*)d_in[iG];
    const float* Be  = (const float*)d_in[iBe];
    float* out = (float*)d_out;

    k_main <<<NB_DIST + 64, 256>>>(XH, XP, XX, W, PW);
    k_topk <<<128, 256>>>(Kp);
    k_bnout<<<NB_BNOUT, 256>>>(PB, G, Be, B, XP, out);
    (void)in_sizes; (void)out_size;
}

// round 13
// speedup vs baseline: 1.1831x; 1.0073x over previous
#include <cuda_runtime.h>
#include <math.h>

#define NN 1024
#define DD 64
#define DPP 32
#define NB_TILE 136
#define NB_BNOUT 64

// ---------------- scratch (device globals) ---------------------------------
__device__ float    g_dH[NN * NN];        // 4 MB pairwise H distances (mirrored)
__device__ float    g_dP[NN * NN];        // 4 MB pairwise P distances (mirrored)
__device__ unsigned g_mask [NN * 32];     // row-major top-K bitset (fully overwritten)
__device__ unsigned g_maskT[NN * 32];     // transposed bitset (atomicOr; zeroed in k_main)
__device__ float    g_x[NN * DD];         // XX @ weight
__device__ float    g_y[NN * DD];         // x @ psi_w^T
__device__ float    g_bmxH[NB_TILE];      // per-H-block max
__device__ float    g_bmxP[NB_TILE];      // per-P-block max
__device__ float    g_bnp[NB_BNOUT][2][DD];  // per-block BN partials (s1, s2)
__device__ unsigned g_arrive;             // bnout arrival counter (zeroed in k_main)

// ---------------- 1. merged: H-dist | P-dist | xy+init (336 blocks) --------
__global__ __launch_bounds__(256)
void k_main(const float* __restrict__ XH, const float* __restrict__ XP,
            const float* __restrict__ XX, const float* __restrict__ W,
            const float* __restrict__ PW) {
    __shared__ float pool[10304];         // 41.2 KB, phase-aliased
    __shared__ float sNA[64], sNB[64];
    __shared__ unsigned smx[8];
    int t = threadIdx.x;
    int bid = blockIdx.x;

    if (bid >= 2 * NB_TILE) {
        // ---------------- xy body + init ----------------
        int xb = bid - 2 * NB_TILE;       // 0..63
        int gt = xb * 256 + t;            // 16384 threads
        g_maskT[gt * 2]     = 0u;
        g_maskT[gt * 2 + 1] = 0u;
        if (gt == 0) g_arrive = 0u;

        float* sW  = pool;                // [k*64+d], 4096
        float* sPW = pool + 4096;         // [d*65+k], 4160 (padded)
        float* sXX = pool + 8256;         // 1024
        float* sx  = pool + 9280;         // 1024
        int row0 = xb * 16;

        for (int idx = t; idx < 4096; idx += 256) sW[idx] = W[idx];
        for (int idx = t; idx < 4096; idx += 256) {
            int d = idx >> 6, k = idx & 63;
            sPW[d * 65 + k] = PW[idx];
        }
        for (int idx = t; idx < 1024; idx += 256) sXX[idx] = XX[row0 * 64 + idx];
        __syncthreads();

        int d = t & 63, rg = t >> 6;
        float acc[4] = {0.f, 0.f, 0.f, 0.f};
        #pragma unroll
        for (int k = 0; k < 64; ++k) {
            float wv = sW[k * 64 + d];
            #pragma unroll
            for (int rr = 0; rr < 4; ++rr) acc[rr] += sXX[(rg * 4 + rr) * 64 + k] * wv;
        }
        #pragma unroll
        for (int rr = 0; rr < 4; ++rr) {
            sx[(rg * 4 + rr) * 64 + d] = acc[rr];
            g_x[(row0 + rg * 4 + rr) * 64 + d] = acc[rr];
        }
        __syncthreads();

        float a2[4] = {0.f, 0.f, 0.f, 0.f};
        #pragma unroll
        for (int k = 0; k < 64; ++k) {
            float pw = sPW[d * 65 + k];
            #pragma unroll
            for (int rr = 0; rr < 4; ++rr) a2[rr] += sx[(rg * 4 + rr) * 64 + k] * pw;
        }
        #pragma unroll
        for (int rr = 0; rr < 4; ++rr) g_y[(row0 + rg * 4 + rr) * 64 + d] = a2[rr];
        return;
    }

    // ---------------- dist body: one feature family per block --------------
    int isH = (bid < NB_TILE);
    int tid = isH ? bid : bid - NB_TILE;
    int by = 0, rem = tid;
    while (rem >= 16 - by) { rem -= 16 - by; ++by; }
    int bx = by + rem;
    int i0 = by * 64, j0 = bx * 64;
    int tx = t & 15, ty = t >> 4;

    float acc[4][4];
    #pragma unroll
    for (int a = 0; a < 4; ++a)
        #pragma unroll
        for (int b = 0; b < 4; ++b) acc[a][b] = 0.f;

    if (isH) {
        const float sig = (float)(0.1 + 2.220446049250313e-16);  // sigma + f64 eps
        float (*sA)[65] = (float(*)[65])pool;
        float (*sB)[65] = (float(*)[65])(pool + 64 * 65);
        for (int idx = t; idx < 4096; idx += 256) {
            int r = idx >> 6, d = idx & 63;
            sA[r][d] = XH[(i0 + r) * 64 + d] / sig;
            sB[r][d] = XH[(j0 + r) * 64 + d] / sig;
        }
        __syncthreads();

        // row norms (threads 0..127, 4 partial chains)
        if (t < 128) {
            const float* rp = (t < 64) ? &sA[t][0] : &sB[t - 64][0];
            float n0 = 0.f, n1 = 0.f, n2 = 0.f, n3 = 0.f;
            #pragma unroll
            for (int d = 0; d < 64; d += 4) {
                n0 += rp[d] * rp[d];
                n1 += rp[d + 1] * rp[d + 1];
                n2 += rp[d + 2] * rp[d + 2];
                n3 += rp[d + 3] * rp[d + 3];
            }
            float nv = (n0 + n1) + (n2 + n3);
            if (t < 64) sNA[t] = nv; else sNB[t - 64] = nv;
        }

        #pragma unroll 8
        for (int d = 0; d < 64; ++d) {
            float rI[4], rJ[4];
            #pragma unroll
            for (int a = 0; a < 4; ++a) rI[a] = sA[ty + 16 * a][d];
            #pragma unroll
            for (int b = 0; b < 4; ++b) rJ[b] = sB[tx + 16 * b][d];
            #pragma unroll
            for (int a = 0; a < 4; ++a)
                #pragma unroll
                for (int b = 0; b < 4; ++b)
                    acc[a][b] += rI[a] * rJ[b];
        }
    } else {
        float (*pA)[33] = (float(*)[33])pool;
        float (*pB)[33] = (float(*)[33])(pool + 64 * 33);
        for (int idx = t; idx < 2048; idx += 256) {
            int r = idx >> 5, p = idx & 31;
            pA[r][p] = XP[(i0 + r) * 32 + p];
            pB[r][p] = XP[(j0 + r) * 32 + p];
        }
        __syncthreads();

        if (t < 128) {
            const float* rp = (t < 64) ? &pA[t][0] : &pB[t - 64][0];
            float n0 = 0.f, n1 = 0.f, n2 = 0.f, n3 = 0.f;
            #pragma unroll
            for (int p = 0; p < 32; p += 4) {
                n0 += rp[p] * rp[p];
                n1 += rp[p + 1] * rp[p + 1];
                n2 += rp[p + 2] * rp[p + 2];
                n3 += rp[p + 3] * rp[p + 3];
            }
            float nv = (n0 + n1) + (n2 + n3);
            if (t < 64) sNA[t] = nv; else sNB[t - 64] = nv;
        }

        #pragma unroll 8
        for (int p = 0; p < 32; ++p) {
            float rI[4], rJ[4];
            #pragma unroll
            for (int a = 0; a < 4; ++a) rI[a] = pA[ty + 16 * a][p];
            #pragma unroll
            for (int b = 0; b < 4; ++b) rJ[b] = pB[tx + 16 * b][p];
            #pragma unroll
            for (int a = 0; a < 4; ++a)
                #pragma unroll
                for (int b = 0; b < 4; ++b)
                    acc[a][b] += rI[a] * rJ[b];
        }
    }
    __syncthreads();                      // norms visible

    float* dst = isH ? g_dH : g_dP;

    // d = sqrt(max(nI + nJ - 2*dot, 0)), write, per-block max
    float nA[4], nB[4];
    #pragma unroll
    for (int a = 0; a < 4; ++a) nA[a] = sNA[ty + 16 * a];
    #pragma unroll
    for (int b = 0; b < 4; ++b) nB[b] = sNB[tx + 16 * b];

    float res[4][4];
    unsigned lmx = 0u;
    #pragma unroll
    for (int a = 0; a < 4; ++a)
        #pragma unroll
        for (int b = 0; b < 4; ++b) {
            float dv = sqrtf(fmaxf(nA[a] + nB[b] - 2.f * acc[a][b], 0.f));
            res[a][b] = dv;
            lmx = max(lmx, __float_as_uint(dv));
            dst[(i0 + ty + 16 * a) * NN + (j0 + tx + 16 * b)] = dv;
        }
    lmx = __reduce_max_sync(0xffffffffu, lmx);
    if ((t & 31) == 0) smx[t >> 5] = lmx;
    __syncthreads();
    if (t == 0) {
        unsigned h = 0u;
        #pragma unroll
        for (int wv = 0; wv < 8; ++wv) h = max(h, smx[wv]);
        if (isH) g_bmxH[tid] = __uint_as_float(h);
        else     g_bmxP[tid] = __uint_as_float(h);
    }

    // mirror tile via shared transpose (coalesced both ways)
    if (bx != by) {
        __syncthreads();
        float (*st)[65] = (float(*)[65])pool;
        #pragma unroll
        for (int a = 0; a < 4; ++a)
            #pragma unroll
            for (int b = 0; b < 4; ++b)
                st[tx + 16 * b][ty + 16 * a] = res[a][b];
        __syncthreads();
        for (int idx = t; idx < 4096; idx += 256) {
            int r = idx >> 6, c = idx & 63;
            dst[(j0 + r) * NN + (i0 + c)] = st[r][c];
        }
    }
}

// ---------------- 2. fused WW + exact top-K (one warp per row) -------------
__global__ void k_topk(const int* __restrict__ Kp) {
    __shared__ unsigned sredH[8], sredP[8];
    int t = threadIdx.x, lane = t & 31, w = t >> 5;
    int i = blockIdx.x * 8 + w;

    // reduce per-block maxes -> global max (prologue)
    {
        unsigned h = 0u, p = 0u;
        if (t < NB_TILE) {
            h = __float_as_uint(g_bmxH[t]);
            p = __float_as_uint(g_bmxP[t]);
        }
        h = __reduce_max_sync(0xffffffffu, h);
        p = __reduce_max_sync(0xffffffffu, p);
        if (lane == 0) { sredH[w] = h; sredP[w] = p; }
    }
    __syncthreads();
    unsigned hh = 0u, pp = 0u;
    #pragma unroll
    for (int s = 0; s < 8; ++s) { hh = max(hh, sredH[s]); pp = max(pp, sredP[s]); }
    float invH = 0.5f / __uint_as_float(hh);   // min is exactly 0 (diagonal)
    float invP = 1.0f / __uint_as_float(pp);

    // load row, compute WW keys (WW > 0 -> float bits are uint-ordered)
    unsigned key[32];
    #pragma unroll
    for (int s = 0; s < 32; ++s) {
        float dh = g_dH[i * NN + s * 32 + lane];
        float dp = g_dP[i * NN + s * 32 + lane];
        float ww = expf(-dh * invH) + 0.2f * expf(-dp * invP);
        key[s] = __float_as_uint(ww);
    }

    int K = Kp ? Kp[0] : 16;
    if (K < 1) K = 1; if (K > NN) K = NN;

    unsigned mrow = 0u;                   // lane L accumulates mask word L
    for (int it = 0; it < K; ++it) {
        unsigned lm = 0u;
        #pragma unroll
        for (int s = 0; s < 32; ++s) lm = max(lm, key[s]);
        unsigned wm = __reduce_max_sync(0xffffffffu, lm);
        // lowest j holding wm (exact jax tie semantics)
        int jc = 0x7fffffff;
        #pragma unroll
        for (int s = 0; s < 32; ++s)
            if (key[s] == wm && s * 32 + lane < jc) jc = s * 32 + lane;
        int jmin = __reduce_min_sync(0xffffffffu, (unsigned)jc);
        // remove from owner lane WITHOUT dynamic register indexing (no spill)
        int ssel = jmin >> 5;
        if (lane == (jmin & 31)) {
            #pragma unroll
            for (int s = 0; s < 32; ++s)
                if (s == ssel) key[s] = 0u;
        }
        if (lane == ssel) mrow |= 1u << (jmin & 31);
        if (lane == 0)
            atomicOr(&g_maskT[jmin * 32 + (i >> 5)], 1u << (i & 31));
    }
    g_mask[i * 32 + lane] = mrow;
}

// ---------------- 3. merged deg + BN + output (64 co-resident blocks) ------
__global__ void k_bnout(const float* __restrict__ psi_b, const float* __restrict__ gamma,
                        const float* __restrict__ beta, const float* __restrict__ bias,
                        const float* __restrict__ XP, float* __restrict__ out) {
    __shared__ int   sc[16], sdg[16];
    __shared__ float sp1[16][64], sp2[16][64];
    __shared__ float ss1[4][64], ss2[4][64];
    __shared__ float smu[64], sistd[64], sg[64], sb[64], sbi[64], spb[64];
    int t = threadIdx.x, lane = t & 31, w = t >> 5;
    int j0 = blockIdx.x * 16;

    // phase A: degrees + diag for own 16 j's (warp w: 2 j's, loads batched)
    {
        int ja = j0 + w * 2, jb = ja + 1;
        unsigned ma = g_mask[ja * 32 + lane] | g_maskT[ja * 32 + lane];
        unsigned mb = g_mask[jb * 32 + lane] | g_maskT[jb * 32 + lane];
        int ca = __reduce_add_sync(0xffffffffu, __popc(ma));
        int cb = __reduce_add_sync(0xffffffffu, __popc(mb));
        int da = __shfl_sync(0xffffffffu, (int)((ma >> (ja & 31)) & 1u), ja >> 5);
        int db = __shfl_sync(0xffffffffu, (int)((mb >> (jb & 31)) & 1u), jb >> 5);
        if (lane == 0) {
            sc[ja - j0] = ca; sc[jb - j0] = cb;
            sdg[ja - j0] = da; sdg[jb - j0] = db;
        }
    }
    __syncthreads();

    // phase B: BN partials over own 16 rows (float4 per thread)
    int q = blockIdx.x * 256 + t;         // global float4 slot; j = q>>4 in [j0, j0+16)
    int jl = t >> 4, d0 = (t & 15) * 4;
    float4 y4 = ((const float4*)g_y)[q];
    {
        float c = (float)sc[jl];
        float yv[4] = {y4.x, y4.y, y4.z, y4.w};
        #pragma unroll
        for (int u = 0; u < 4; ++u) {
            float bb = psi_b[d0 + u];
            sp1[jl][d0 + u] = yv[u] * ((float)NN + c);
            float h1 = yv[u] + bb, h2 = 2.f * yv[u] + bb;
            sp2[jl][d0 + u] = ((float)NN - c) * h1 * h1 + c * h2 * h2;
        }
    }
    __syncthreads();
    {
        int d = t & 63, rg = t >> 6;
        float a1 = sp1[rg][d] + sp1[rg + 4][d] + sp1[rg + 8][d] + sp1[rg + 12][d];
        float a2 = sp2[rg][d] + sp2[rg + 4][d] + sp2[rg + 8][d] + sp2[rg + 12][d];
        ss1[rg][d] = a1; ss2[rg][d] = a2;
    }
    __syncthreads();
    if (t < 64) {
        g_bnp[blockIdx.x][0][t] = ss1[0][t] + ss1[1][t] + ss1[2][t] + ss1[3][t];
        g_bnp[blockIdx.x][1][t] = ss2[0][t] + ss2[1][t] + ss2[2][t] + ss2[3][t];
    }
    __syncthreads();
    if (t == 0) {
        __threadfence();                  // release partials
        atomicAdd(&g_arrive, 1u);
        while (*(volatile unsigned*)&g_arrive < NB_BNOUT) { }   // all 64 co-resident
        __threadfence();                  // acquire partials
    }
    __syncthreads();

    // phase C: redundant parallel finalize (32 KB L2-hot per block)
    if (t < 64) {
        float s1 = 0.f, s2 = 0.f;
        #pragma unroll 4
        for (int bl = 0; bl < NB_BNOUT; ++bl) {
            s1 += g_bnp[bl][0][t];
            s2 += g_bnp[bl][1][t];
        }
        const float invN2 = 1.0f / ((float)NN * (float)NN);
        float mu  = psi_b[t] + s1 * invN2;
        float var = s2 * invN2 - mu * mu;
        smu[t]   = mu;
        sistd[t] = rsqrtf(var + 1e-5f);
        sg[t] = gamma[t]; sb[t] = beta[t]; sbi[t] = bias[t]; spb[t] = psi_b[t];
    }
    __syncthreads();

    // phase D: output slice (rows == own degree rows)
    float4 x4 = ((const float4*)g_x)[q];
    float dg = (float)sdg[jl], c = (float)sc[jl];
    float yv[4] = {y4.x, y4.y, y4.z, y4.w};
    float xv[4] = {x4.x, x4.y, x4.z, x4.w};
    float4 o4;
    float* ov = (float*)&o4;
    #pragma unroll
    for (int u = 0; u < 4; ++u) {
        int d = d0 + u;
        float z = (2.f * yv[u] + spb[d] - smu[d]) * sistd[d] * sg[d] + sb[d];
        float s = 1.0f / (1.0f + expf(-z));
        ov[u] = xv[u] * (dg + (c - dg) * s) + sbi[d];
    }
    ((float4*)out)[q] = o4;                               // out[:, :DH] segment
    ((float4*)(out + NN * DD + NN * DPP))[q] = o4;        // full out segment
    if (q < NN * DPP / 4)
        ((float4*)(out + NN * DD))[q] = ((const float4*)XP)[q];  // XP passthrough
}

// ---------------- launch ----------------------------------------------------
extern "C" void kernel_launch(void* const* d_in, const int* in_sizes, int n_in,
                              void* d_out, int out_size) {
    // expected order: XH, XP, XX, K, weight, bias, psi_w, psi_b, gamma, beta
    int iXH = 0, iXP = 1, iXX = 2, iK = 3, iW = 4, iB = 5, iPW = 6, iPB = 7, iG = 8, iBe = 9;
    if (n_in == 9) {  // K dropped as a scalar
        iK = -1; iW = 3; iB = 4; iPW = 5; iPB = 6; iG = 7; iBe = 8;
    }
    const float* XH  = (const float*)d_in[iXH];
    const float* XP  = (const float*)d_in[iXP];
    const float* XX  = (const float*)d_in[iXX];
    const int*   Kp  = (iK >= 0) ? (const int*)d_in[iK] : nullptr;
    const float* W   = (const float*)d_in[iW];
    const float* B   = (const float*)d_in[iB];
    const float* PW  = (const float*)d_in[iPW];
    const float* PB  = (const float*)d_in[iPB];
    const float* G   = (const float*)d_in[iG];
    const float* Be  = (const float*)d_in[iBe];
    float* out = (float*)d_out;

    k_main <<<2 * NB_TILE + 64, 256>>>(XH, XP, XX, W, PW);
    k_topk <<<128, 256>>>(Kp);
    k_bnout<<<NB_BNOUT, 256>>>(PB, G, Be, B, XP, out);
    (void)in_sizes; (void)out_size;
}